// round 6
// baseline (speedup 1.0000x reference)
#include <cuda_runtime.h>
#include <cuda_bf16.h>
#include <cstdint>

// ===========================================================================
// GRU cell via mma.sync (sm_103 non-'a' target: tcgen05 unavailable).
// 3-term bf16 split: C = Ah*Bh + Al*Bh + Ah*Bl  (~2^-17 effective precision).
// One pack kernel emits bf16 hi/lo planes in ldmatrix-ready layout; main
// kernel is a 4-accumulator fused GEMM (r, z, n_i, n_h) + gate epilogue.
//   CTA tile M=128 x N=64, 512 threads = 16 warps (4m x 4n), warp m32 x n16.
//   3-stage cp.async pipeline, ONE __syncthreads per chunk.
//   Mainloop scheduled for HMMA dependency distance 12 (gate-interleaved).
// ===========================================================================

#define NT_COUNT 8           // 512 / 64
#define MT_COUNT 128         // 16384 / 128
#define NSTAGE 3

// packed A: [mt 128][chunk 32][plane 2][row 128][64B]  = 64 MB
// packed W: [nt 8][gate 3][chunk 32][plane 2][n 64][64B] = 6 MB
__device__ __align__(128) unsigned char g_Apack[128u * 32u * 2u * 128u * 64u];
__device__ __align__(128) unsigned char g_Wpack[8u * 3u * 32u * 2u * 64u * 64u];

// smem stage layout (stride 80B rows -> conflict-free ldmatrix):
//   A plane p:        p*10240 + r*80          (128 rows)
//   B gate g plane p: 20480 + ((g*2+p)*64 + n)*80
#define STAGE_BYTES 51200
#define SMEM_TOTAL (NSTAGE * STAGE_BYTES)   // 153600

__device__ __forceinline__ uint32_t smem_u32(const void* p) {
    uint32_t a;
    asm("{ .reg .u64 t; cvta.to.shared.u64 t, %1; cvt.u32.u64 %0, t; }"
        : "=r"(a) : "l"(p));
    return a;
}

__device__ __forceinline__ void cp16(uint32_t dst, const void* src) {
    asm volatile("cp.async.cg.shared.global [%0], [%1], 16;"
                 :: "r"(dst), "l"(src) : "memory");
}
__device__ __forceinline__ void cp_commit() {
    asm volatile("cp.async.commit_group;" ::: "memory");
}
template <int N> __device__ __forceinline__ void cp_wait() {
    asm volatile("cp.async.wait_group %0;" :: "n"(N) : "memory");
}

__device__ __forceinline__ void ldm4(uint32_t r[4], uint32_t addr) {
    asm volatile("ldmatrix.sync.aligned.m8n8.x4.shared.b16 {%0,%1,%2,%3}, [%4];"
                 : "=r"(r[0]), "=r"(r[1]), "=r"(r[2]), "=r"(r[3]) : "r"(addr));
}

__device__ __forceinline__ void mma16(float c[4], const uint32_t a[4],
                                      uint32_t b0, uint32_t b1) {
    asm volatile(
        "mma.sync.aligned.m16n8k16.row.col.f32.bf16.bf16.f32 "
        "{%0,%1,%2,%3}, {%4,%5,%6,%7}, {%8,%9}, {%0,%1,%2,%3};\n"
        : "+f"(c[0]), "+f"(c[1]), "+f"(c[2]), "+f"(c[3])
        : "r"(a[0]), "r"(a[1]), "r"(a[2]), "r"(a[3]), "r"(b0), "r"(b1));
}

__device__ __forceinline__ uint32_t pack_hi(float a, float b, uint32_t& lo) {
    __nv_bfloat16 ha = __float2bfloat16(a);
    __nv_bfloat16 hb = __float2bfloat16(b);
    float ra = a - __bfloat162float(ha);
    float rb = b - __bfloat162float(hb);
    __nv_bfloat162 hw; hw.x = ha; hw.y = hb;
    __nv_bfloat162 lw = __floats2bfloat162_rn(ra, rb);
    lo = *reinterpret_cast<uint32_t*>(&lw);
    return *reinterpret_cast<uint32_t*>(&hw);
}

// ---------------------------------------------------------------------------
// Merged pack kernel. Blocks [0,4096): A part (c = bx&31, mt = bx>>5).
// Blocks [4096,4864): W part (c = w&31, ntg = w>>5; nt = ntg/3, g = ntg%3).
__global__ __launch_bounds__(256) void pack_all(
    const float* __restrict__ x, const float* __restrict__ hs,
    const float* __restrict__ Wir, const float* __restrict__ Whr,
    const float* __restrict__ Wiz, const float* __restrict__ Whz,
    const float* __restrict__ Win, const float* __restrict__ Whn) {
    __shared__ float stg[32][65];
    const int bx = blockIdx.x;
    if (bx < 4096) {
        const int c = bx & 31, mt = bx >> 5;
        const float* S = (c < 16) ? x : hs;
        const int k0 = (c & 15) * 32;
        const size_t mrow = (size_t)mt * 128;
        unsigned char* hiP = g_Apack + ((size_t)(mt * 32 + c) * 2) * 8192;
        unsigned char* loP = hiP + 8192;
        #pragma unroll
        for (int it = 0; it < 8; ++it) {
            int id = it * 256 + threadIdx.x;   // 2048 float2
            int r = id >> 4, w = id & 15;
            float2 v = *reinterpret_cast<const float2*>(
                S + (mrow + r) * 512 + k0 + 2 * w);
            uint32_t lo, hi = pack_hi(v.x, v.y, lo);
            *reinterpret_cast<uint32_t*>(hiP + r * 64 + w * 4) = hi;
            *reinterpret_cast<uint32_t*>(loP + r * 64 + w * 4) = lo;
        }
    } else {
        const int w = bx - 4096;
        const int c = w & 31;
        const int ntg = w >> 5;                // 0..23
        const int nt = ntg / 3, g = ntg % 3;
        const float* W = (c < 16)
            ? ((g == 0) ? Wir : (g == 1) ? Wiz : Win)
            : ((g == 0) ? Whr : (g == 1) ? Whz : Whn);
        const int k0 = (c & 15) * 32, n0 = nt * 64;
        #pragma unroll
        for (int it = 0; it < 8; ++it) {       // 2048 floats: 32k x 64n
            int id = it * 256 + threadIdx.x;
            int k = id >> 6, n = id & 63;
            stg[k][n] = W[(size_t)(k0 + k) * 512 + n0 + n];
        }
        __syncthreads();
        unsigned char* hiP = g_Wpack + ((size_t)((nt * 3 + g) * 32 + c) * 2) * 4096;
        unsigned char* loP = hiP + 4096;
        #pragma unroll
        for (int it = 0; it < 4; ++it) {       // 1024 word-pairs
            int id = it * 256 + threadIdx.x;
            int n = id >> 4, q = id & 15;
            uint32_t lo, hi = pack_hi(stg[2 * q][n], stg[2 * q + 1][n], lo);
            *reinterpret_cast<uint32_t*>(hiP + n * 64 + q * 4) = hi;
            *reinterpret_cast<uint32_t*>(loP + n * 64 + q * 4) = lo;
        }
    }
}

// ---------------------------------------------------------------------------
// issue one stage: 2560 cp16 ops, 512 threads -> 5 iterations.
__device__ __forceinline__ void issue_stage(uint32_t sbase, int nt, int mt, int c) {
    const int tid = threadIdx.x;
    const unsigned char* Ac = g_Apack + ((size_t)(mt * 32 + c) * 2) * 8192;
    const unsigned char* Wc = g_Wpack + ((size_t)(nt * 3 * 32) * 2) * 4096;
    #pragma unroll
    for (int it = 0; it < 5; ++it) {
        int id = it * 512 + tid;
        if (id < 1024) {                       // A: plane(2) x row(128) x ch(4)
            int p = id >> 9, rem = id & 511;
            int r = rem >> 2, ch = rem & 3;
            cp16(sbase + p * 10240 + r * 80 + ch * 16,
                 Ac + p * 8192 + r * 64 + ch * 16);
        } else {                               // B: gp(6) x n(64) x ch(4)
            int v = id - 1024;
            int gp = v >> 8, rem = v & 255;
            int n = rem >> 2, ch = rem & 3;
            int g = gp >> 1, p = gp & 1;
            cp16(sbase + 20480 + (gp * 64 + n) * 80 + ch * 16,
                 Wc + ((size_t)(g * 32 + c) * 2 + p) * 4096 + n * 64 + ch * 16);
        }
    }
}

// 4 independent-accumulator mma burst (one term, one gate).
#define T4(ACC, A0, A1, B)                                            \
    do {                                                              \
        mma16(ACC[0][0], A0, B[0], B[1]);                             \
        mma16(ACC[0][1], A0, B[2], B[3]);                             \
        mma16(ACC[1][0], A1, B[0], B[1]);                             \
        mma16(ACC[1][1], A1, B[2], B[3]);                             \
    } while (0)

__device__ __forceinline__ void compute_chunk(
    uint32_t sbase, int wm, int wn, int lane,
    float accR[2][2][4], float accZ[2][2][4], float accN[2][2][4]) {
    const int rowA = (lane & 7) + ((lane >> 3) & 1) * 8;
    const int kbA  = (lane >> 4) * 16;
    const int rowB = (lane & 7) + (lane >> 4) * 8;
    const int kbB  = ((lane >> 3) & 1) * 16;
    const uint32_t aAddr = sbase + (wm + rowA) * 80 + kbA;
    const uint32_t bAddr = sbase + 20480 + (wn + rowB) * 80 + kbB;

    #pragma unroll
    for (int ks = 0; ks < 2; ++ks) {
        // ---- front-load A (hi+lo) and all 3 gates' B-hi fragments ----
        uint32_t Ah0[4], Ah1[4], Al0[4], Al1[4];
        uint32_t BhR[4], BhZ[4], BhN[4];
        ldm4(Ah0, aAddr + ks * 32);
        ldm4(Ah1, aAddr + ks * 32 + 1280);          // +16 rows
        ldm4(Al0, aAddr + ks * 32 + 10240);         // lo plane
        ldm4(Al1, aAddr + ks * 32 + 10240 + 1280);
        ldm4(BhR, bAddr + ks * 32);                 // gate r hi
        ldm4(BhZ, bAddr + ks * 32 + 10240);         // gate z hi
        ldm4(BhN, bAddr + ks * 32 + 20480);         // gate n hi

        // term 1: Ah x Bh  (12 mma, acc reuse distance 12)
        T4(accR, Ah0, Ah1, BhR);
        T4(accZ, Ah0, Ah1, BhZ);
        T4(accN, Ah0, Ah1, BhN);

        // B-lo loads issued here; latency hidden under term 2
        uint32_t BlR[4], BlZ[4], BlN[4];
        ldm4(BlR, bAddr + ks * 32 + 5120);
        ldm4(BlZ, bAddr + ks * 32 + 15360);
        ldm4(BlN, bAddr + ks * 32 + 25600);

        // term 2: Al x Bh
        T4(accR, Al0, Al1, BhR);
        T4(accZ, Al0, Al1, BhZ);
        T4(accN, Al0, Al1, BhN);

        // term 3: Ah x Bl
        T4(accR, Ah0, Ah1, BlR);
        T4(accZ, Ah0, Ah1, BlZ);
        T4(accN, Ah0, Ah1, BlN);
    }
}

__global__ void __launch_bounds__(512, 1) gru_main(
    const float* __restrict__ hs,
    const float* __restrict__ br, const float* __restrict__ bz,
    const float* __restrict__ bn, float* __restrict__ out) {
    extern __shared__ unsigned char smem_raw[];
    const uint32_t smem = smem_u32(smem_raw);

    const int tid = threadIdx.x;
    const int wid = tid >> 5, lane = tid & 31;
    const int wm = (wid & 3) * 32;
    const int wn = (wid >> 2) * 16;       // 0..3 -> 0,16,32,48
    const int nt = blockIdx.x;            // 0..7
    const int mt = blockIdx.y;            // 0..127

    float aR[2][2][4] = {}, aZ[2][2][4] = {}, aNi[2][2][4] = {}, aNh[2][2][4] = {};

    issue_stage(smem, nt, mt, 0);
    cp_commit();
    issue_stage(smem + STAGE_BYTES, nt, mt, 1);
    cp_commit();

    // Single-sync multistage:
    //   wait(stage c) -> sync (all warps done with stage c-1)
    //   -> issue stage c+2 into buffer (c+2)%3 -> compute stage c.
    int sidx = 0;                  // c % 3
    for (int c = 0; c < 32; ++c) {
        if (c + 1 < 32) cp_wait<1>(); else cp_wait<0>();
        __syncthreads();
        if (c + 2 < 32) {
            int widx = sidx + 2 >= NSTAGE ? sidx + 2 - NSTAGE : sidx + 2;
            issue_stage(smem + widx * STAGE_BYTES, nt, mt, c + 2);
            cp_commit();
        }
        const uint32_t sbase = smem + sidx * STAGE_BYTES;
        if (c < 16) compute_chunk(sbase, wm, wn, lane, aR, aZ, aNi);
        else        compute_chunk(sbase, wm, wn, lane, aR, aZ, aNh);
        sidx = (sidx + 1 >= NSTAGE) ? 0 : sidx + 1;
    }

    // ---- epilogue ----
    #pragma unroll
    for (int mi = 0; mi < 2; ++mi)
    #pragma unroll
    for (int ni = 0; ni < 2; ++ni)
    #pragma unroll
    for (int i = 0; i < 4; ++i) {
        int rr = mt * 128 + wm + mi * 16 + (lane >> 2) + ((i >> 1) << 3);
        int cc = nt * 64 + wn + ni * 8 + 2 * (lane & 3) + (i & 1);
        float pr = aR[mi][ni][i] + __ldg(br + cc);
        float pz = aZ[mi][ni][i] + __ldg(bz + cc);
        float rg = 1.0f / (1.0f + __expf(-pr));
        float zg = 1.0f / (1.0f + __expf(-pz));
        float ng = tanhf(aNi[mi][ni][i] + rg * aNh[mi][ni][i] + __ldg(bn + cc));
        float hv = hs[(size_t)rr * 512 + cc];
        out[(size_t)rr * 512 + cc] = (1.0f - zg) * ng + zg * hv;
    }
}

// ---------------------------------------------------------------------------
extern "C" void kernel_launch(void* const* d_in, const int* in_sizes, int n_in,
                              void* d_out, int out_size) {
    (void)in_sizes; (void)n_in; (void)out_size;
    const float* x   = (const float*)d_in[0];
    const float* h   = (const float*)d_in[1];
    const float* Wir = (const float*)d_in[2];
    const float* Whr = (const float*)d_in[3];
    const float* br  = (const float*)d_in[4];
    const float* Wiz = (const float*)d_in[5];
    const float* Whz = (const float*)d_in[6];
    const float* bz  = (const float*)d_in[7];
    const float* Win = (const float*)d_in[8];
    const float* Whn = (const float*)d_in[9];
    const float* bn  = (const float*)d_in[10];

    static_assert(SMEM_TOTAL == 153600, "smem layout");
    cudaFuncSetAttribute(gru_main, cudaFuncAttributeMaxDynamicSharedMemorySize,
                         SMEM_TOTAL);
    cudaFuncSetAttribute(gru_main, cudaFuncAttributePreferredSharedMemoryCarveout,
                         cudaSharedmemCarveoutMaxShared);

    pack_all<<<4864, 256>>>(x, h, Wir, Whr, Wiz, Whz, Win, Whn);
    gru_main<<<dim3(NT_COUNT, MT_COUNT), 512, SMEM_TOTAL>>>(
        h, br, bz, bn, (float*)d_out);
}

// round 7
// speedup vs baseline: 1.1173x; 1.1173x over previous
#include <cuda_runtime.h>
#include <cuda_bf16.h>
#include <cstdint>

// ===========================================================================
// GRU cell via mma.sync (sm_103 non-'a' target: tcgen05 unavailable).
// 3-term bf16 split: C = Ah*Bh + Al*Bh + Ah*Bl  (~2^-17 effective precision).
// One pack kernel emits bf16 hi/lo planes in ldmatrix-ready layout; main
// kernel is a 4-accumulator fused GEMM (r, z, n_i, n_h) + gate epilogue.
//   CTA tile M=128 x N=64, 512 threads = 16 warps (4m x 4n), warp m32 x n16.
//   2-stage cp.async pipeline, K=64 per stage -> 16 barriers total.
//   cp.async issue placed mid-stage so the tensor queue stays fed.
// ===========================================================================

#define NT_COUNT 8           // 512 / 64
#define MT_COUNT 128         // 16384 / 128

// packed A: [mt 128][chunk 32][plane 2][row 128][64B]  = 64 MB
// packed W: [nt 8][gate 3][chunk 32][plane 2][n 64][64B] = 6 MB
__device__ __align__(128) unsigned char g_Apack[128u * 32u * 2u * 128u * 64u];
__device__ __align__(128) unsigned char g_Wpack[8u * 3u * 32u * 2u * 64u * 64u];

// smem stage layout, 144B row stride (36 banks -> conflict-free ldmatrix):
//   A plane p:  p*18432 + r*144                  (128 rows, 128B data)
//   B gate g plane p: 36864 + ((g*2+p)*64 + n)*144
#define ROWB 144
#define STAGE_BYTES 92160
#define SMEM_TOTAL (2 * STAGE_BYTES)   // 184320

__device__ __forceinline__ uint32_t smem_u32(const void* p) {
    uint32_t a;
    asm("{ .reg .u64 t; cvta.to.shared.u64 t, %1; cvt.u32.u64 %0, t; }"
        : "=r"(a) : "l"(p));
    return a;
}

__device__ __forceinline__ void cp16(uint32_t dst, const void* src) {
    asm volatile("cp.async.cg.shared.global [%0], [%1], 16;"
                 :: "r"(dst), "l"(src) : "memory");
}
__device__ __forceinline__ void cp_commit() {
    asm volatile("cp.async.commit_group;" ::: "memory");
}
template <int N> __device__ __forceinline__ void cp_wait() {
    asm volatile("cp.async.wait_group %0;" :: "n"(N) : "memory");
}

__device__ __forceinline__ void ldm4(uint32_t r[4], uint32_t addr) {
    asm volatile("ldmatrix.sync.aligned.m8n8.x4.shared.b16 {%0,%1,%2,%3}, [%4];"
                 : "=r"(r[0]), "=r"(r[1]), "=r"(r[2]), "=r"(r[3]) : "r"(addr));
}

__device__ __forceinline__ void mma16(float c[4], const uint32_t a[4],
                                      uint32_t b0, uint32_t b1) {
    asm volatile(
        "mma.sync.aligned.m16n8k16.row.col.f32.bf16.bf16.f32 "
        "{%0,%1,%2,%3}, {%4,%5,%6,%7}, {%8,%9}, {%0,%1,%2,%3};\n"
        : "+f"(c[0]), "+f"(c[1]), "+f"(c[2]), "+f"(c[3])
        : "r"(a[0]), "r"(a[1]), "r"(a[2]), "r"(a[3]), "r"(b0), "r"(b1));
}

__device__ __forceinline__ uint32_t pack_hi(float a, float b, uint32_t& lo) {
    __nv_bfloat16 ha = __float2bfloat16(a);
    __nv_bfloat16 hb = __float2bfloat16(b);
    float ra = a - __bfloat162float(ha);
    float rb = b - __bfloat162float(hb);
    __nv_bfloat162 hw; hw.x = ha; hw.y = hb;
    __nv_bfloat162 lw = __floats2bfloat162_rn(ra, rb);
    lo = *reinterpret_cast<uint32_t*>(&lw);
    return *reinterpret_cast<uint32_t*>(&hw);
}

// ---------------------------------------------------------------------------
// Merged pack kernel. Blocks [0,4096): A part (c = bx&31, mt = bx>>5).
// Blocks [4096,4864): W part (c = w&31, ntg = w>>5; nt = ntg/3, g = ntg%3).
__global__ __launch_bounds__(256) void pack_all(
    const float* __restrict__ x, const float* __restrict__ hs,
    const float* __restrict__ Wir, const float* __restrict__ Whr,
    const float* __restrict__ Wiz, const float* __restrict__ Whz,
    const float* __restrict__ Win, const float* __restrict__ Whn) {
    __shared__ float stg[32][65];
    const int bx = blockIdx.x;
    if (bx < 4096) {
        const int c = bx & 31, mt = bx >> 5;
        const float* S = (c < 16) ? x : hs;
        const int k0 = (c & 15) * 32;
        const size_t mrow = (size_t)mt * 128;
        unsigned char* hiP = g_Apack + ((size_t)(mt * 32 + c) * 2) * 8192;
        unsigned char* loP = hiP + 8192;
        #pragma unroll
        for (int it = 0; it < 8; ++it) {
            int id = it * 256 + threadIdx.x;   // 2048 float2
            int r = id >> 4, w = id & 15;
            float2 v = *reinterpret_cast<const float2*>(
                S + (mrow + r) * 512 + k0 + 2 * w);
            uint32_t lo, hi = pack_hi(v.x, v.y, lo);
            *reinterpret_cast<uint32_t*>(hiP + r * 64 + w * 4) = hi;
            *reinterpret_cast<uint32_t*>(loP + r * 64 + w * 4) = lo;
        }
    } else {
        const int w = bx - 4096;
        const int c = w & 31;
        const int ntg = w >> 5;                // 0..23
        const int nt = ntg / 3, g = ntg % 3;
        const float* W = (c < 16)
            ? ((g == 0) ? Wir : (g == 1) ? Wiz : Win)
            : ((g == 0) ? Whr : (g == 1) ? Whz : Whn);
        const int k0 = (c & 15) * 32, n0 = nt * 64;
        #pragma unroll
        for (int it = 0; it < 8; ++it) {       // 2048 floats: 32k x 64n
            int id = it * 256 + threadIdx.x;
            int k = id >> 6, n = id & 63;
            stg[k][n] = W[(size_t)(k0 + k) * 512 + n0 + n];
        }
        __syncthreads();
        unsigned char* hiP = g_Wpack + ((size_t)((nt * 3 + g) * 32 + c) * 2) * 4096;
        unsigned char* loP = hiP + 4096;
        #pragma unroll
        for (int it = 0; it < 4; ++it) {       // 1024 word-pairs
            int id = it * 256 + threadIdx.x;
            int n = id >> 4, q = id & 15;
            uint32_t lo, hi = pack_hi(stg[2 * q][n], stg[2 * q + 1][n], lo);
            *reinterpret_cast<uint32_t*>(hiP + n * 64 + q * 4) = hi;
            *reinterpret_cast<uint32_t*>(loP + n * 64 + q * 4) = lo;
        }
    }
}

// ---------------------------------------------------------------------------
// issue one stage (chunks 2s, 2s+1): 5120 cp16 ops, 512 threads -> 10 iters.
// SMEM row r holds k64: bytes [0,64) from chunk 2s, [64,128) from chunk 2s+1.
__device__ __forceinline__ void issue_stage(uint32_t sbase, int nt, int mt, int s) {
    const int tid = threadIdx.x;
    const int c0 = 2 * s;
    const unsigned char* Ac = g_Apack + ((size_t)(mt * 32 + c0) * 2) * 8192;
    #pragma unroll
    for (int it = 0; it < 10; ++it) {
        int id = it * 512 + tid;
        if (id < 2048) {                       // A: plane(2) x row(128) x ch(8)
            int p = id >> 10, rem = id & 1023;
            int r = rem >> 3, ch = rem & 7;
            int half = ch >> 2, cho = ch & 3;
            cp16(sbase + p * 18432 + r * ROWB + ch * 16,
                 Ac + (half * 2 + p) * 8192 + r * 64 + cho * 16);
        } else {                               // B: gp(6) x n(64) x ch(8)
            int v = id - 2048;
            int gp = v >> 9, rem = v & 511;
            int n = rem >> 3, ch = rem & 7;
            int half = ch >> 2, cho = ch & 3;
            int g = gp >> 1, p = gp & 1;
            cp16(sbase + 36864 + (gp * 64 + n) * ROWB + ch * 16,
                 g_Wpack + (((size_t)((nt * 3 + g) * 32 + c0 + half)) * 2 + p) * 4096
                         + n * 64 + cho * 16);
        }
    }
}

#define GATE_MMA(ACC, BH, BL)                                         \
    do {                                                              \
        mma16(ACC[0][0], Ah0, BH[0], BH[1]);                          \
        mma16(ACC[0][1], Ah0, BH[2], BH[3]);                          \
        mma16(ACC[1][0], Ah1, BH[0], BH[1]);                          \
        mma16(ACC[1][1], Ah1, BH[2], BH[3]);                          \
        mma16(ACC[0][0], Al0, BH[0], BH[1]);                          \
        mma16(ACC[0][1], Al0, BH[2], BH[3]);                          \
        mma16(ACC[1][0], Al1, BH[0], BH[1]);                          \
        mma16(ACC[1][1], Al1, BH[2], BH[3]);                          \
        mma16(ACC[0][0], Ah0, BL[0], BL[1]);                          \
        mma16(ACC[0][1], Ah0, BL[2], BL[3]);                          \
        mma16(ACC[1][0], Ah1, BL[0], BL[1]);                          \
        mma16(ACC[1][1], Ah1, BL[2], BL[3]);                          \
    } while (0)

// One k16 step: 10 ldm4 + 36 mma, R5 scheduling (per-gate ldm then burst).
__device__ __forceinline__ void compute_ks(
    uint32_t aAddr, uint32_t bAddr,
    float accR[2][2][4], float accZ[2][2][4], float accN[2][2][4]) {
    uint32_t Ah0[4], Ah1[4], Al0[4], Al1[4];
    ldm4(Ah0, aAddr);
    ldm4(Ah1, aAddr + 16 * ROWB);               // +16 rows
    ldm4(Al0, aAddr + 18432);                   // lo plane
    ldm4(Al1, aAddr + 18432 + 16 * ROWB);

    uint32_t Bh[4], Bl[4];
    // gate r (g=0): hi at +0, lo at +9216
    ldm4(Bh, bAddr);
    ldm4(Bl, bAddr + 9216);
    GATE_MMA(accR, Bh, Bl);
    // gate z (g=1): +18432 / +27648
    ldm4(Bh, bAddr + 18432);
    ldm4(Bl, bAddr + 27648);
    GATE_MMA(accZ, Bh, Bl);
    // gate n (g=2): +36864 / +46080
    ldm4(Bh, bAddr + 36864);
    ldm4(Bl, bAddr + 46080);
    GATE_MMA(accN, Bh, Bl);
}

__global__ void __launch_bounds__(512, 1) gru_main(
    const float* __restrict__ hs,
    const float* __restrict__ br, const float* __restrict__ bz,
    const float* __restrict__ bn, float* __restrict__ out) {
    extern __shared__ unsigned char smem_raw[];
    const uint32_t smem = smem_u32(smem_raw);

    const int tid = threadIdx.x;
    const int wid = tid >> 5, lane = tid & 31;
    const int wm = (wid & 3) * 32;
    const int wn = (wid >> 2) * 16;       // 0..3 -> 0,16,32,48
    const int nt = blockIdx.x;            // 0..7
    const int mt = blockIdx.y;            // 0..127

    const int rowA = (lane & 7) + ((lane >> 3) & 1) * 8;
    const int kbA  = (lane >> 4) * 16;
    const int rowB = (lane & 7) + (lane >> 4) * 8;
    const int kbB  = ((lane >> 3) & 1) * 16;
    const uint32_t aOff = (uint32_t)(wm + rowA) * ROWB + kbA;
    const uint32_t bOff = 36864u + (uint32_t)(wn + rowB) * ROWB + kbB;

    float aR[2][2][4] = {}, aZ[2][2][4] = {}, aNi[2][2][4] = {}, aNh[2][2][4] = {};

    issue_stage(smem, nt, mt, 0);
    cp_commit();

    // 2-stage: wait(s) -> sync -> compute ks0 -> issue(s+1) -> compute ks1..3
    for (int s = 0; s < 16; ++s) {
        cp_wait<0>();
        __syncthreads();
        const uint32_t sbase = smem + (s & 1) * STAGE_BYTES;
        const uint32_t aA = sbase + aOff;
        const uint32_t bA = sbase + bOff;
        if (s < 8) compute_ks(aA, bA, aR, aZ, aNi);
        else       compute_ks(aA, bA, aR, aZ, aNh);
        if (s + 1 < 16) {
            issue_stage(smem + ((s + 1) & 1) * STAGE_BYTES, nt, mt, s + 1);
            cp_commit();
        }
        #pragma unroll
        for (int ks = 1; ks < 4; ++ks) {
            if (s < 8) compute_ks(aA + ks * 32, bA + ks * 32, aR, aZ, aNi);
            else       compute_ks(aA + ks * 32, bA + ks * 32, aR, aZ, aNh);
        }
    }

    // ---- epilogue ----
    #pragma unroll
    for (int mi = 0; mi < 2; ++mi)
    #pragma unroll
    for (int ni = 0; ni < 2; ++ni)
    #pragma unroll
    for (int i = 0; i < 4; ++i) {
        int rr = mt * 128 + wm + mi * 16 + (lane >> 2) + ((i >> 1) << 3);
        int cc = nt * 64 + wn + ni * 8 + 2 * (lane & 3) + (i & 1);
        float pr = aR[mi][ni][i] + __ldg(br + cc);
        float pz = aZ[mi][ni][i] + __ldg(bz + cc);
        float rg = 1.0f / (1.0f + __expf(-pr));
        float zg = 1.0f / (1.0f + __expf(-pz));
        float ng = tanhf(aNi[mi][ni][i] + rg * aNh[mi][ni][i] + __ldg(bn + cc));
        float hv = hs[(size_t)rr * 512 + cc];
        out[(size_t)rr * 512 + cc] = (1.0f - zg) * ng + zg * hv;
    }
}

// ---------------------------------------------------------------------------
extern "C" void kernel_launch(void* const* d_in, const int* in_sizes, int n_in,
                              void* d_out, int out_size) {
    (void)in_sizes; (void)n_in; (void)out_size;
    const float* x   = (const float*)d_in[0];
    const float* h   = (const float*)d_in[1];
    const float* Wir = (const float*)d_in[2];
    const float* Whr = (const float*)d_in[3];
    const float* br  = (const float*)d_in[4];
    const float* Wiz = (const float*)d_in[5];
    const float* Whz = (const float*)d_in[6];
    const float* bz  = (const float*)d_in[7];
    const float* Win = (const float*)d_in[8];
    const float* Whn = (const float*)d_in[9];
    const float* bn  = (const float*)d_in[10];

    static_assert(SMEM_TOTAL == 184320, "smem layout");
    cudaFuncSetAttribute(gru_main, cudaFuncAttributeMaxDynamicSharedMemorySize,
                         SMEM_TOTAL);
    cudaFuncSetAttribute(gru_main, cudaFuncAttributePreferredSharedMemoryCarveout,
                         cudaSharedmemCarveoutMaxShared);

    pack_all<<<4864, 256>>>(x, h, Wir, Whr, Wiz, Whz, Win, Whn);
    gru_main<<<dim3(NT_COUNT, MT_COUNT), 512, SMEM_TOTAL>>>(
        h, br, bz, bn, (float*)d_out);
}

// round 8
// speedup vs baseline: 1.1217x; 1.0040x over previous
#include <cuda_runtime.h>
#include <cuda_bf16.h>
#include <cstdint>

// ===========================================================================
// GRU cell via mma.sync (sm_103 non-'a' target: tcgen05 unavailable).
// 3-term bf16 split: C = Ah*Bh + Al*Bh + Ah*Bl  (~2^-17 effective precision).
// One pack kernel emits bf16 hi/lo planes in ldmatrix-ready layout; main
// kernel is a 4-accumulator fused GEMM (r, z, n_i, n_h) + gate epilogue.
//   CTA tile M=64 x N=64, 256 threads = 8 warps (2m x 4n), warp m32 x n16.
//   2-stage cp.async pipeline (K=32/stage), 80KB smem -> 2 CTAs/SM,
//   32 warps/SM for latency hiding at unchanged per-thread register cost.
// ===========================================================================

#define NT_COUNT 8           // 512 / 64
#define MT_COUNT 256         // 16384 / 64

// packed A: [mt 256][chunk 32][plane 2][row 64][64B]  = 64 MB
// packed W: [nt 8][gate 3][chunk 32][plane 2][n 64][64B] = 6 MB
__device__ __align__(128) unsigned char g_Apack[256u * 32u * 2u * 64u * 64u];
__device__ __align__(128) unsigned char g_Wpack[8u * 3u * 32u * 2u * 64u * 64u];

// smem stage layout, 80B row stride (20 banks -> conflict-free ldmatrix):
//   A plane p:        p*5120 + r*80            (64 rows, 64B data)
//   B gate g plane p: 10240 + ((g*2+p)*64 + n)*80
#define ROWB 80
#define STAGE_BYTES 40960
#define SMEM_TOTAL (2 * STAGE_BYTES)   // 81920 -> 2 CTAs/SM (164KB/228KB)

__device__ __forceinline__ uint32_t smem_u32(const void* p) {
    uint32_t a;
    asm("{ .reg .u64 t; cvta.to.shared.u64 t, %1; cvt.u32.u64 %0, t; }"
        : "=r"(a) : "l"(p));
    return a;
}

__device__ __forceinline__ void cp16(uint32_t dst, const void* src) {
    asm volatile("cp.async.cg.shared.global [%0], [%1], 16;"
                 :: "r"(dst), "l"(src) : "memory");
}
__device__ __forceinline__ void cp_commit() {
    asm volatile("cp.async.commit_group;" ::: "memory");
}
template <int N> __device__ __forceinline__ void cp_wait() {
    asm volatile("cp.async.wait_group %0;" :: "n"(N) : "memory");
}

__device__ __forceinline__ void ldm4(uint32_t r[4], uint32_t addr) {
    asm volatile("ldmatrix.sync.aligned.m8n8.x4.shared.b16 {%0,%1,%2,%3}, [%4];"
                 : "=r"(r[0]), "=r"(r[1]), "=r"(r[2]), "=r"(r[3]) : "r"(addr));
}

__device__ __forceinline__ void mma16(float c[4], const uint32_t a[4],
                                      uint32_t b0, uint32_t b1) {
    asm volatile(
        "mma.sync.aligned.m16n8k16.row.col.f32.bf16.bf16.f32 "
        "{%0,%1,%2,%3}, {%4,%5,%6,%7}, {%8,%9}, {%0,%1,%2,%3};\n"
        : "+f"(c[0]), "+f"(c[1]), "+f"(c[2]), "+f"(c[3])
        : "r"(a[0]), "r"(a[1]), "r"(a[2]), "r"(a[3]), "r"(b0), "r"(b1));
}

__device__ __forceinline__ uint32_t pack_hi(float a, float b, uint32_t& lo) {
    __nv_bfloat16 ha = __float2bfloat16(a);
    __nv_bfloat16 hb = __float2bfloat16(b);
    float ra = a - __bfloat162float(ha);
    float rb = b - __bfloat162float(hb);
    __nv_bfloat162 hw; hw.x = ha; hw.y = hb;
    __nv_bfloat162 lw = __floats2bfloat162_rn(ra, rb);
    lo = *reinterpret_cast<uint32_t*>(&lw);
    return *reinterpret_cast<uint32_t*>(&hw);
}

// ---------------------------------------------------------------------------
// Merged pack kernel. Blocks [0,4096): A part (c = bx&31, mt128 = bx>>5 covers
// two 64-row main tiles). Blocks [4096,4864): W part (unchanged, N-tile 64).
__global__ __launch_bounds__(256) void pack_all(
    const float* __restrict__ x, const float* __restrict__ hs,
    const float* __restrict__ Wir, const float* __restrict__ Whr,
    const float* __restrict__ Wiz, const float* __restrict__ Whz,
    const float* __restrict__ Win, const float* __restrict__ Whn) {
    __shared__ float stg[32][65];
    const int bx = blockIdx.x;
    if (bx < 4096) {
        const int c = bx & 31, mt128 = bx >> 5;
        const float* S = (c < 16) ? x : hs;
        const int k0 = (c & 15) * 32;
        const size_t mrow = (size_t)mt128 * 128;
        #pragma unroll
        for (int it = 0; it < 8; ++it) {
            int id = it * 256 + threadIdx.x;   // 2048 float2
            int r = id >> 4, w = id & 15;      // r in [0,128)
            float2 v = *reinterpret_cast<const float2*>(
                S + (mrow + r) * 512 + k0 + 2 * w);
            uint32_t lo, hi = pack_hi(v.x, v.y, lo);
            int mt64 = mt128 * 2 + (r >> 6);
            int rl = r & 63;
            unsigned char* hiP = g_Apack + ((size_t)(mt64 * 32 + c) * 2) * 4096;
            *reinterpret_cast<uint32_t*>(hiP + rl * 64 + w * 4) = hi;
            *reinterpret_cast<uint32_t*>(hiP + 4096 + rl * 64 + w * 4) = lo;
        }
    } else {
        const int w = bx - 4096;
        const int c = w & 31;
        const int ntg = w >> 5;                // 0..23
        const int nt = ntg / 3, g = ntg % 3;
        const float* W = (c < 16)
            ? ((g == 0) ? Wir : (g == 1) ? Wiz : Win)
            : ((g == 0) ? Whr : (g == 1) ? Whz : Whn);
        const int k0 = (c & 15) * 32, n0 = nt * 64;
        #pragma unroll
        for (int it = 0; it < 8; ++it) {       // 2048 floats: 32k x 64n
            int id = it * 256 + threadIdx.x;
            int k = id >> 6, n = id & 63;
            stg[k][n] = W[(size_t)(k0 + k) * 512 + n0 + n];
        }
        __syncthreads();
        unsigned char* hiP = g_Wpack + ((size_t)((nt * 3 + g) * 32 + c) * 2) * 4096;
        unsigned char* loP = hiP + 4096;
        #pragma unroll
        for (int it = 0; it < 4; ++it) {       // 1024 word-pairs
            int id = it * 256 + threadIdx.x;
            int n = id >> 4, q = id & 15;
            uint32_t lo, hi = pack_hi(stg[2 * q][n], stg[2 * q + 1][n], lo);
            *reinterpret_cast<uint32_t*>(hiP + n * 64 + q * 4) = hi;
            *reinterpret_cast<uint32_t*>(loP + n * 64 + q * 4) = lo;
        }
    }
}

// ---------------------------------------------------------------------------
// issue one stage (chunk c): 2048 cp16 ops, 256 threads -> 8 iterations.
__device__ __forceinline__ void issue_stage(uint32_t sbase, int nt, int mt, int c) {
    const int tid = threadIdx.x;
    const unsigned char* Ac = g_Apack + ((size_t)(mt * 32 + c) * 2) * 4096;
    #pragma unroll
    for (int it = 0; it < 8; ++it) {
        int id = it * 256 + tid;
        if (id < 512) {                        // A: plane(2) x row(64) x ch(4)
            int p = id >> 8, rem = id & 255;
            int r = rem >> 2, ch = rem & 3;
            cp16(sbase + p * 5120 + r * ROWB + ch * 16,
                 Ac + p * 4096 + r * 64 + ch * 16);
        } else {                               // B: gp(6) x n(64) x ch(4)
            int v = id - 512;
            int gp = v >> 8, rem = v & 255;
            int n = rem >> 2, ch = rem & 3;
            int g = gp >> 1, p = gp & 1;
            cp16(sbase + 10240 + (gp * 64 + n) * ROWB + ch * 16,
                 g_Wpack + (((size_t)((nt * 3 + g) * 32 + c)) * 2 + p) * 4096
                         + n * 64 + ch * 16);
        }
    }
}

#define GATE_MMA(ACC, BH, BL)                                         \
    do {                                                              \
        mma16(ACC[0][0], Ah0, BH[0], BH[1]);                          \
        mma16(ACC[0][1], Ah0, BH[2], BH[3]);                          \
        mma16(ACC[1][0], Ah1, BH[0], BH[1]);                          \
        mma16(ACC[1][1], Ah1, BH[2], BH[3]);                          \
        mma16(ACC[0][0], Al0, BH[0], BH[1]);                          \
        mma16(ACC[0][1], Al0, BH[2], BH[3]);                          \
        mma16(ACC[1][0], Al1, BH[0], BH[1]);                          \
        mma16(ACC[1][1], Al1, BH[2], BH[3]);                          \
        mma16(ACC[0][0], Ah0, BL[0], BL[1]);                          \
        mma16(ACC[0][1], Ah0, BL[2], BL[3]);                          \
        mma16(ACC[1][0], Ah1, BL[0], BL[1]);                          \
        mma16(ACC[1][1], Ah1, BL[2], BL[3]);                          \
    } while (0)

// One k16 step: 10 ldm4 + 36 mma (R5 scheduling: per-gate ldm then burst).
__device__ __forceinline__ void compute_ks(
    uint32_t aAddr, uint32_t bAddr,
    float accR[2][2][4], float accZ[2][2][4], float accN[2][2][4]) {
    uint32_t Ah0[4], Ah1[4], Al0[4], Al1[4];
    ldm4(Ah0, aAddr);
    ldm4(Ah1, aAddr + 16 * ROWB);               // +16 rows
    ldm4(Al0, aAddr + 5120);                    // lo plane
    ldm4(Al1, aAddr + 5120 + 16 * ROWB);

    uint32_t Bh[4], Bl[4];
    // gate r (g=0): hi at +0, lo at +5120
    ldm4(Bh, bAddr);
    ldm4(Bl, bAddr + 5120);
    GATE_MMA(accR, Bh, Bl);
    // gate z (g=1): +10240 / +15360
    ldm4(Bh, bAddr + 10240);
    ldm4(Bl, bAddr + 15360);
    GATE_MMA(accZ, Bh, Bl);
    // gate n (g=2): +20480 / +25600
    ldm4(Bh, bAddr + 20480);
    ldm4(Bl, bAddr + 25600);
    GATE_MMA(accN, Bh, Bl);
}

__global__ void __launch_bounds__(256, 2) gru_main(
    const float* __restrict__ hs,
    const float* __restrict__ br, const float* __restrict__ bz,
    const float* __restrict__ bn, float* __restrict__ out) {
    extern __shared__ unsigned char smem_raw[];
    const uint32_t smem = smem_u32(smem_raw);

    const int tid = threadIdx.x;
    const int wid = tid >> 5, lane = tid & 31;
    const int wm = (wid & 1) * 32;        // 0,32
    const int wn = (wid >> 1) * 16;       // 0,16,32,48
    const int nt = blockIdx.x;            // 0..7
    const int mt = blockIdx.y;            // 0..255

    const int rowA = (lane & 7) + ((lane >> 3) & 1) * 8;
    const int kbA  = (lane >> 4) * 16;
    const int rowB = (lane & 7) + (lane >> 4) * 8;
    const int kbB  = ((lane >> 3) & 1) * 16;
    const uint32_t aOff = (uint32_t)(wm + rowA) * ROWB + kbA;
    const uint32_t bOff = 10240u + (uint32_t)(wn + rowB) * ROWB + kbB;

    float aR[2][2][4] = {}, aZ[2][2][4] = {}, aNi[2][2][4] = {}, aNh[2][2][4] = {};

    issue_stage(smem, nt, mt, 0);
    cp_commit();

    // 2-stage: wait(c) -> sync -> compute ks0 -> issue(c+1) -> compute ks1
    for (int c = 0; c < 32; ++c) {
        cp_wait<0>();
        __syncthreads();
        const uint32_t sbase = smem + (c & 1) * STAGE_BYTES;
        const uint32_t aA = sbase + aOff;
        const uint32_t bA = sbase + bOff;
        if (c < 16) compute_ks(aA, bA, aR, aZ, aNi);
        else        compute_ks(aA, bA, aR, aZ, aNh);
        if (c + 1 < 32) {
            issue_stage(smem + ((c + 1) & 1) * STAGE_BYTES, nt, mt, c + 1);
            cp_commit();
        }
        if (c < 16) compute_ks(aA + 32, bA + 32, aR, aZ, aNi);
        else        compute_ks(aA + 32, bA + 32, aR, aZ, aNh);
    }

    // ---- epilogue ----
    #pragma unroll
    for (int mi = 0; mi < 2; ++mi)
    #pragma unroll
    for (int ni = 0; ni < 2; ++ni)
    #pragma unroll
    for (int i = 0; i < 4; ++i) {
        int rr = mt * 64 + wm + mi * 16 + (lane >> 2) + ((i >> 1) << 3);
        int cc = nt * 64 + wn + ni * 8 + 2 * (lane & 3) + (i & 1);
        float pr = aR[mi][ni][i] + __ldg(br + cc);
        float pz = aZ[mi][ni][i] + __ldg(bz + cc);
        float rg = 1.0f / (1.0f + __expf(-pr));
        float zg = 1.0f / (1.0f + __expf(-pz));
        float ng = tanhf(aNi[mi][ni][i] + rg * aNh[mi][ni][i] + __ldg(bn + cc));
        float hv = hs[(size_t)rr * 512 + cc];
        out[(size_t)rr * 512 + cc] = (1.0f - zg) * ng + zg * hv;
    }
}

// ---------------------------------------------------------------------------
extern "C" void kernel_launch(void* const* d_in, const int* in_sizes, int n_in,
                              void* d_out, int out_size) {
    (void)in_sizes; (void)n_in; (void)out_size;
    const float* x   = (const float*)d_in[0];
    const float* h   = (const float*)d_in[1];
    const float* Wir = (const float*)d_in[2];
    const float* Whr = (const float*)d_in[3];
    const float* br  = (const float*)d_in[4];
    const float* Wiz = (const float*)d_in[5];
    const float* Whz = (const float*)d_in[6];
    const float* bz  = (const float*)d_in[7];
    const float* Win = (const float*)d_in[8];
    const float* Whn = (const float*)d_in[9];
    const float* bn  = (const float*)d_in[10];

    static_assert(SMEM_TOTAL == 81920, "smem layout");
    cudaFuncSetAttribute(gru_main, cudaFuncAttributeMaxDynamicSharedMemorySize,
                         SMEM_TOTAL);
    cudaFuncSetAttribute(gru_main, cudaFuncAttributePreferredSharedMemoryCarveout,
                         cudaSharedmemCarveoutMaxShared);

    pack_all<<<4864, 256>>>(x, h, Wir, Whr, Wiz, Whz, Win, Whn);
    gru_main<<<dim3(NT_COUNT, MT_COUNT), 256, SMEM_TOTAL>>>(
        h, br, bz, bn, (float*)d_out);
}